// round 8
// baseline (speedup 1.0000x reference)
#include <cuda_runtime.h>
#include <math.h>

#define NN 768

// ---------------- scratch ----------------
__device__ float g_q[64*NN], g_k[64*NN], g_vT[NN*64];
__device__ float g_A[128*NN], g_B[128*NN];
__device__ float g_avp[4*64*NN], g_g1[128*NN];
__device__ float g_Wp[128*64], g_bp[128];
__device__ float g_sA[128], g_qA[128], g_sB[128], g_qB[128];   // stage-2 stats accums
__device__ float g_sG[128], g_qG[128];                         // bn1d stats accums

// ---------------- helpers ----------------
__device__ __forceinline__ float wsum(float v) {
    #pragma unroll
    for (int o = 16; o; o >>= 1) v += __shfl_xor_sync(0xffffffffu, v, o);
    return v;
}

// wT[i*16+r] = W[(o0+r)*ldw + koff + i]
__device__ __forceinline__ void fill_W16(float* wT, const float* __restrict__ W,
                                         int ldw, int o0, int koff) {
    for (int v = threadIdx.x; v < 1024; v += 256) {
        int i = v >> 4, r = v & 15;
        wT[v] = W[(o0 + r) * ldw + koff + i];
    }
}

// 16 rows x 128 cols, X streamed from global. acc[8].
__device__ __forceinline__ void gemm16d(const float* __restrict__ X, int c0,
                                        const float* wT, float acc[8]) {
    int c = threadIdx.x & 127, rg = threadIdx.x >> 7;
    const float* xp = X + c0 + c;
    const float* wp = wT + rg * 8;
    #pragma unroll 8
    for (int i = 0; i < 64; i++) {
        float x = __ldg(xp + i * NN);
        float4 w0 = *(const float4*)(wp + i * 16);
        float4 w1 = *(const float4*)(wp + i * 16 + 4);
        acc[0] = fmaf(w0.x, x, acc[0]); acc[1] = fmaf(w0.y, x, acc[1]);
        acc[2] = fmaf(w0.z, x, acc[2]); acc[3] = fmaf(w0.w, x, acc[3]);
        acc[4] = fmaf(w1.x, x, acc[4]); acc[5] = fmaf(w1.y, x, acc[5]);
        acc[6] = fmaf(w1.z, x, acc[6]); acc[7] = fmaf(w1.w, x, acc[7]);
    }
}

// Same, applying relu(nb[i].x * x + nb[i].y) on load.
__device__ __forceinline__ void gemm16d_norm(const float* __restrict__ X, int c0,
                                             const float* wT, const float2* nb,
                                             float acc[8]) {
    int c = threadIdx.x & 127, rg = threadIdx.x >> 7;
    const float* xp = X + c0 + c;
    const float* wp = wT + rg * 8;
    #pragma unroll 8
    for (int i = 0; i < 64; i++) {
        float2 sb = nb[i];
        float x = fmaxf(fmaf(sb.x, __ldg(xp + i * NN), sb.y), 0.f);
        float4 w0 = *(const float4*)(wp + i * 16);
        float4 w1 = *(const float4*)(wp + i * 16 + 4);
        acc[0] = fmaf(w0.x, x, acc[0]); acc[1] = fmaf(w0.y, x, acc[1]);
        acc[2] = fmaf(w0.z, x, acc[2]); acc[3] = fmaf(w0.w, x, acc[3]);
        acc[4] = fmaf(w1.x, x, acc[4]); acc[5] = fmaf(w1.y, x, acc[5]);
        acc[6] = fmaf(w1.z, x, acc[6]); acc[7] = fmaf(w1.w, x, acc[7]);
    }
}

// X = sum of 4 split-k partials at stride S.
template<int S>
__device__ __forceinline__ void gemm16d_s4(const float* __restrict__ X, int c0,
                                           const float* wT, float acc[8]) {
    int c = threadIdx.x & 127, rg = threadIdx.x >> 7;
    const float* xp = X + c0 + c;
    const float* wp = wT + rg * 8;
    #pragma unroll 4
    for (int i = 0; i < 64; i++) {
        float x = (__ldg(xp + i * NN) + __ldg(xp + i * NN + S)) +
                  (__ldg(xp + i * NN + 2 * S) + __ldg(xp + i * NN + 3 * S));
        float4 w0 = *(const float4*)(wp + i * 16);
        float4 w1 = *(const float4*)(wp + i * 16 + 4);
        acc[0] = fmaf(w0.x, x, acc[0]); acc[1] = fmaf(w0.y, x, acc[1]);
        acc[2] = fmaf(w0.z, x, acc[2]); acc[3] = fmaf(w0.w, x, acc[3]);
        acc[4] = fmaf(w1.x, x, acc[4]); acc[5] = fmaf(w1.y, x, acc[5]);
        acc[6] = fmaf(w1.z, x, acc[6]); acc[7] = fmaf(w1.w, x, acc[7]);
    }
}

// Per-row (16 rows/block) sum & sumsq of vals -> atomicAdd into sdst/qdst.
__device__ __forceinline__ void rowstats_atomic(const float vals[8], int o0,
                                                float* sdst, float* qdst) {
    __shared__ float rs[16][4], rq[16][4];
    int wid = threadIdx.x >> 5, lane = threadIdx.x & 31;
    int rg = threadIdx.x >> 7;
    #pragma unroll
    for (int r = 0; r < 8; r++) {
        float s = vals[r], s2 = vals[r] * vals[r];
        s = wsum(s); s2 = wsum(s2);
        if (lane == 0) { rs[rg * 8 + r][wid & 3] = s; rq[rg * 8 + r][wid & 3] = s2; }
    }
    __syncthreads();
    if (threadIdx.x < 16) {
        float s  = rs[threadIdx.x][0] + rs[threadIdx.x][1] + rs[threadIdx.x][2] + rs[threadIdx.x][3];
        float q2 = rq[threadIdx.x][0] + rq[threadIdx.x][1] + rq[threadIdx.x][2] + rq[threadIdx.x][3];
        atomicAdd(&sdst[o0 + threadIdx.x], s);
        atomicAdd(&qdst[o0 + threadIdx.x], q2);
    }
}

// ---------------- kernels ----------------

// q,k,v convs (v transposed) + W' = cw1[:,64:]@mhw, b' + zero stats accums. Grid 89.
__global__ void k_qkv(const float* __restrict__ d1, const float* __restrict__ d2,
                      const float* __restrict__ qw, const float* __restrict__ qb,
                      const float* __restrict__ kw, const float* __restrict__ kb,
                      const float* __restrict__ vw, const float* __restrict__ vb,
                      const float* __restrict__ mhw, const float* __restrict__ mhb,
                      const float* __restrict__ cw1, const float* __restrict__ cb1)
{
    __shared__ float wT[64 * 16];
    int b = blockIdx.x;
    int tid = threadIdx.x;
    if (b < 72) {
        int grp = b / 24, lb = b % 24;
        int o0 = (lb / 6) * 16, c0 = (lb % 6) * 128;
        const float *W, *X, *Bb;
        if (grp == 0)      { W = qw; X = d1; Bb = qb; }
        else if (grp == 1) { W = kw; X = d2; Bb = kb; }
        else               { W = vw; X = d2; Bb = vb; }
        fill_W16(wT, W, 64, o0, 0);
        __syncthreads();
        float acc[8] = {};
        gemm16d(X, c0, wT, acc);
        int c = tid & 127, rg = tid >> 7;
        int obase = o0 + rg * 8;
        if (grp < 2) {
            float* Y = (grp == 0) ? g_q : g_k;
            #pragma unroll
            for (int r = 0; r < 8; r++)
                Y[(obase + r) * NN + c0 + c] = acc[r] + Bb[obase + r];
        } else {
            int n = c0 + c;
            float4 v0, v1;
            v0.x = acc[0] + Bb[obase + 0]; v0.y = acc[1] + Bb[obase + 1];
            v0.z = acc[2] + Bb[obase + 2]; v0.w = acc[3] + Bb[obase + 3];
            v1.x = acc[4] + Bb[obase + 4]; v1.y = acc[5] + Bb[obase + 5];
            v1.z = acc[6] + Bb[obase + 6]; v1.w = acc[7] + Bb[obase + 7];
            *(float4*)&g_vT[n * 64 + obase]     = v0;
            *(float4*)&g_vT[n * 64 + obase + 4] = v1;
        }
    } else if (b < 88) {
        // W'[row, d] = sum_i cw1[row, 64+i] * mhw[i, d]; 8 rows per block.
        int r0 = (b - 72) * 8;
        int d = tid & 63, rg = tid >> 6;
        int row = r0 + rg * 2;
        float a0 = 0.f, a1 = 0.f;
        #pragma unroll 8
        for (int i = 0; i < 64; i++) {
            float x = __ldg(mhw + i * 64 + d);
            a0 = fmaf(__ldg(cw1 + row * 128 + 64 + i), x, a0);
            a1 = fmaf(__ldg(cw1 + (row + 1) * 128 + 64 + i), x, a1);
        }
        g_Wp[row * 64 + d] = a0;
        g_Wp[(row + 1) * 64 + d] = a1;
    } else {
        if (tid < 128) {
            float s = __ldg(cb1 + tid);
            #pragma unroll 8
            for (int i = 0; i < 64; i++)
                s = fmaf(__ldg(cw1 + tid * 128 + 64 + i), __ldg(mhb + i), s);
            g_bp[tid] = s;
            // zero stats accumulators (k_AB / k_g1 atomics land later in-stream)
            g_sA[tid] = 0.f; g_qA[tid] = 0.f;
            g_sB[tid] = 0.f; g_qB[tid] = 0.f;
            g_sG[tid] = 0.f; g_qG[tid] = 0.f;
        }
    }
}

// A/B GEMM with stage-1 norm computed in prologue, stage-2 stats in epilogue. Grid 96.
__global__ void k_AB(const float* __restrict__ w1, const float* __restrict__ b1,
                     const float* __restrict__ bn1g, const float* __restrict__ bn1b)
{
    __shared__ float wT[64 * 16];
    __shared__ float2 nb[64];
    __shared__ float chs[64], chq[64];
    int b = blockIdx.x;
    int tid = threadIdx.x;
    int half = b / 48, lb = b % 48;
    int o0 = (lb / 6) * 16, c0 = (lb % 6) * 128;
    const float* X = half ? g_k : g_q;
    int wid = tid >> 5, lane = tid & 31;

    // stage-1 channel stats: warp w -> channels w*8 .. w*8+7
    #pragma unroll
    for (int ch = 0; ch < 8; ch++) {
        int c = wid * 8 + ch;
        const float* row = X + c * NN;
        float s = 0.f, s2 = 0.f;
        #pragma unroll
        for (int j = 0; j < 24; j++) {
            float x = __ldg(row + lane + j * 32);
            s += x; s2 += x * x;
        }
        s = wsum(s); s2 = wsum(s2);
        if (lane == 0) { chs[c] = s; chq[c] = s2; }
    }
    fill_W16(wT, w1, 128, o0, half ? 64 : 0);
    __syncthreads();
    if (tid < 64) {
        float m = chs[tid] * (1.f / NN);
        float v = chq[tid] * (1.f / NN) - m * m;
        float si = rsqrtf(v + 1e-3f);
        float vn = v * si * si;
        float sb = rsqrtf(vn + 1e-5f);
        float scale = si * sb * __ldg(bn1g + half * 64 + tid);
        nb[tid] = make_float2(scale, -m * scale + __ldg(bn1b + half * 64 + tid));
    }
    __syncthreads();

    float acc[8] = {};
    gemm16d_norm(X, c0, wT, nb, acc);

    int c = tid & 127, rg = tid >> 7;
    int obase = o0 + rg * 8;
    float vals[8];
    if (half == 0) {
        #pragma unroll
        for (int r = 0; r < 8; r++) {
            vals[r] = acc[r];
            g_A[(obase + r) * NN + c0 + c] = vals[r];
        }
    } else {
        #pragma unroll
        for (int r = 0; r < 8; r++) {
            vals[r] = acc[r] + __ldg(b1 + obase + r);
            g_B[(obase + r) * NN + c0 + c] = vals[r];
        }
    }
    __syncthreads();
    rowstats_atomic(vals, o0, half ? g_sB : g_sA, half ? g_qB : g_qA);
}

// score_pre -> out; nc2 + Sk computed in prologue. Grid (12,12) x 512.
__global__ void __launch_bounds__(512)
k_score(const float* __restrict__ w2, const float* __restrict__ shw,
        const float* __restrict__ bn2g, const float* __restrict__ bn2b,
        float* __restrict__ out)
{
    __shared__ float As[64 * 64];
    __shared__ float Bs[64 * 64];
    __shared__ float2 scb[128];
    __shared__ float w2s[128];
    __shared__ float Sks[64];
    int tid = threadIdx.x;
    int n0 = blockIdx.y * 64, m0 = blockIdx.x * 64;
    if (tid < 128) {
        float mA = g_sA[tid] * (1.f / NN), mB = g_sB[tid] * (1.f / NN);
        float vA = g_qA[tid] * (1.f / NN) - mA * mA;
        float vB = g_qB[tid] * (1.f / NN) - mB * mB;
        float m2 = mA + mB, v2 = vA + vB;
        float si = rsqrtf(v2 + 1e-3f);
        float vn = v2 * si * si;
        float sb = rsqrtf(vn + 1e-5f);
        float scale = si * sb * __ldg(bn2g + tid);
        scb[tid] = make_float2(scale, -m2 * scale + __ldg(bn2b + tid));
        w2s[tid] = __ldg(w2 + tid);
    } else if (tid < 192) {
        int m = m0 + tid - 128;
        float s = 0.f;
        #pragma unroll 8
        for (int i = 0; i < 64; i++)
            s = fmaf(__ldg(shw + 64 + i), __ldg(g_k + i * NN + m), s);
        Sks[tid - 128] = s;
    }
    __syncthreads();

    int tx = tid & 15, ty = tid >> 4;
    float acc[2][4] = {};
    #pragma unroll
    for (int ch = 0; ch < 2; ch++) {
        #pragma unroll
        for (int v = tid; v < 1024; v += 512) {
            int o = v >> 4, t4 = (v & 15) << 2;
            int og = ch * 64 + o;
            float2 sb = scb[og];
            float4 a = *(const float4*)&g_A[og * NN + n0 + t4];
            a.x = fmaf(sb.x, a.x, sb.y); a.y = fmaf(sb.x, a.y, sb.y);
            a.z = fmaf(sb.x, a.z, sb.y); a.w = fmaf(sb.x, a.w, sb.y);
            *(float4*)&As[o * 64 + t4] = a;
            float4 bv = *(const float4*)&g_B[og * NN + m0 + t4];
            bv.x *= sb.x; bv.y *= sb.x; bv.z *= sb.x; bv.w *= sb.x;
            *(float4*)&Bs[o * 64 + t4] = bv;
        }
        __syncthreads();
        #pragma unroll 4
        for (int o = 0; o < 64; o++) {
            float2 a = *(const float2*)&As[o * 64 + ty * 2];
            float4 bv = *(const float4*)&Bs[o * 64 + tx * 4];
            float w = w2s[ch * 64 + o];
            acc[0][0] = fmaf(w, fmaxf(a.x + bv.x, 0.f), acc[0][0]);
            acc[0][1] = fmaf(w, fmaxf(a.x + bv.y, 0.f), acc[0][1]);
            acc[0][2] = fmaf(w, fmaxf(a.x + bv.z, 0.f), acc[0][2]);
            acc[0][3] = fmaf(w, fmaxf(a.x + bv.w, 0.f), acc[0][3]);
            acc[1][0] = fmaf(w, fmaxf(a.y + bv.x, 0.f), acc[1][0]);
            acc[1][1] = fmaf(w, fmaxf(a.y + bv.y, 0.f), acc[1][1]);
            acc[1][2] = fmaf(w, fmaxf(a.y + bv.z, 0.f), acc[1][2]);
            acc[1][3] = fmaf(w, fmaxf(a.y + bv.w, 0.f), acc[1][3]);
        }
        __syncthreads();
    }
    // Sq[n] and all constants are per-row shifts -> cancelled by softmax.
    #pragma unroll
    for (int rn = 0; rn < 2; rn++) {
        int n = n0 + ty * 2 + rn;
        float4 o4;
        o4.x = acc[rn][0] + Sks[tx * 4 + 0];
        o4.y = acc[rn][1] + Sks[tx * 4 + 1];
        o4.z = acc[rn][2] + Sks[tx * 4 + 2];
        o4.w = acc[rn][3] + Sks[tx * 4 + 3];
        *(float4*)&out[n * NN + m0 + tx * 4] = o4;
    }
}

// warp-per-row softmax, in place. Grid 96 x 256.
__global__ void k_softmax(float* __restrict__ score)
{
    int row = blockIdx.x * 8 + (threadIdx.x >> 5);
    int lane = threadIdx.x & 31;
    float* p = score + row * NN;
    float v[24];
    float mx = -1e30f;
    #pragma unroll
    for (int i = 0; i < 24; i++) { v[i] = p[lane + i * 32]; mx = fmaxf(mx, v[i]); }
    #pragma unroll
    for (int o = 16; o; o >>= 1) mx = fmaxf(mx, __shfl_xor_sync(0xffffffffu, mx, o));
    float s = 0.f;
    #pragma unroll
    for (int i = 0; i < 24; i++) { v[i] = __expf(v[i] - mx); s += v[i]; }
    s = wsum(s);
    float inv = 1.f / s;
    #pragma unroll
    for (int i = 0; i < 24; i++) p[lane + i * 32] = v[i] * inv;
}

// av partials: 48 n-tiles x 4 k-splits = 192 x 256.
__global__ void k_av(const float* __restrict__ score)
{
    int bx = blockIdx.x;
    int nt = bx % 48, ks = bx / 48;
    int n0 = nt * 16;
    int tid = threadIdx.x;
    __shared__ float Vs[64][64];
    __shared__ float Ps[16][64];
    int d0  = (tid & 31) * 2;
    int nl0 = (tid >> 5) * 2;
    float a00 = 0.f, a01 = 0.f, a10 = 0.f, a11 = 0.f;
    for (int c = 0; c < 3; c++) {
        int mb = ks * 192 + c * 64;
        for (int idx = tid; idx < 64 * 64; idx += 256)
            Vs[idx >> 6][idx & 63] = g_vT[(mb + (idx >> 6)) * 64 + (idx & 63)];
        for (int idx = tid; idx < 16 * 64; idx += 256)
            Ps[idx >> 6][idx & 63] = score[(n0 + (idx >> 6)) * NN + mb + (idx & 63)];
        __syncthreads();
        #pragma unroll 4
        for (int m = 0; m < 64; m++) {
            float2 vv = *(const float2*)&Vs[m][d0];
            float p0 = Ps[nl0][m], p1 = Ps[nl0 + 1][m];
            a00 = fmaf(p0, vv.x, a00); a01 = fmaf(p0, vv.y, a01);
            a10 = fmaf(p1, vv.x, a10); a11 = fmaf(p1, vv.y, a11);
        }
        __syncthreads();
    }
    float* dst = g_avp + ks * (64 * NN);
    dst[d0 * NN + n0 + nl0]           = a00;
    dst[(d0 + 1) * NN + n0 + nl0]     = a01;
    dst[d0 * NN + n0 + nl0 + 1]       = a10;
    dst[(d0 + 1) * NN + n0 + nl0 + 1] = a11;
}

// g1 = cw1[:,:64]@desc1 + W'@(sum of 4 av partials) + b'; bn stats in epilogue. Grid 48.
__global__ void k_g1(const float* __restrict__ cw1, const float* __restrict__ desc1)
{
    __shared__ float wT[64 * 16];
    int lb = blockIdx.x;
    int o0 = (lb / 6) * 16, c0 = (lb % 6) * 128;
    float acc[8] = {};
    fill_W16(wT, cw1, 128, o0, 0);
    __syncthreads();
    gemm16d(desc1, c0, wT, acc);
    __syncthreads();
    fill_W16(wT, g_Wp, 64, o0, 0);
    __syncthreads();
    gemm16d_s4<64 * NN>(g_avp, c0, wT, acc);
    int c = threadIdx.x & 127, rg = threadIdx.x >> 7;
    int obase = o0 + rg * 8;
    float vals[8];
    #pragma unroll
    for (int r = 0; r < 8; r++) {
        vals[r] = acc[r] + g_bp[obase + r];
        g_g1[(obase + r) * NN + c0 + c] = vals[r];
    }
    __syncthreads();
    rowstats_atomic(vals, o0, g_sG, g_qG);
}

// out_desc = desc1 + cw2 @ relu(norm(g1)) + cb2; norm coeffs from accums. Grid 24.
__global__ void k_final(const float* __restrict__ cw2, const float* __restrict__ cb2,
                        const float* __restrict__ cbg, const float* __restrict__ cbb,
                        const float* __restrict__ desc1, float* __restrict__ out)
{
    __shared__ float wT[64 * 16];
    __shared__ float2 ncf[128];
    int lb = blockIdx.x;
    int tid = threadIdx.x;
    int o0 = (lb / 6) * 16, c0 = (lb % 6) * 128;
    if (tid < 128) {
        float m = g_sG[tid] * (1.f / NN);
        float v = g_qG[tid] * (1.f / NN) - m * m;
        float scale = rsqrtf(v + 1e-5f) * __ldg(cbg + tid);
        ncf[tid] = make_float2(scale, -m * scale + __ldg(cbb + tid));
    }
    float acc[8] = {};
    fill_W16(wT, cw2, 128, o0, 0);
    __syncthreads();
    gemm16d_norm(g_g1, c0, wT, ncf, acc);
    __syncthreads();
    fill_W16(wT, cw2, 128, o0, 64);
    __syncthreads();
    gemm16d_norm(g_g1 + 64 * NN, c0, wT, ncf + 64, acc);
    int c = tid & 127, rg = tid >> 7;
    int obase = o0 + rg * 8;
    #pragma unroll
    for (int r = 0; r < 8; r++)
        out[(obase + r) * NN + c0 + c] =
            acc[r] + __ldg(cb2 + obase + r) + __ldg(desc1 + (obase + r) * NN + c0 + c);
}

// ---------------- launch ----------------
extern "C" void kernel_launch(void* const* d_in, const int* in_sizes, int n_in,
                              void* d_out, int out_size)
{
    const float* desc1 = (const float*)d_in[0];
    const float* desc2 = (const float*)d_in[1];
    const float* qw  = (const float*)d_in[2];  const float* qb  = (const float*)d_in[3];
    const float* kw  = (const float*)d_in[4];  const float* kb  = (const float*)d_in[5];
    const float* vw  = (const float*)d_in[6];  const float* vb  = (const float*)d_in[7];
    const float* mhw = (const float*)d_in[8];  const float* mhb = (const float*)d_in[9];
    const float* cw1 = (const float*)d_in[10]; const float* cb1 = (const float*)d_in[11];
    const float* cbg = (const float*)d_in[12]; const float* cbb = (const float*)d_in[13];
    const float* cw2 = (const float*)d_in[14]; const float* cb2 = (const float*)d_in[15];
    const float* shw = (const float*)d_in[16];
    const float* bn1g = (const float*)d_in[18]; const float* bn1b = (const float*)d_in[19];
    const float* sw1 = (const float*)d_in[20]; const float* sb1 = (const float*)d_in[21];
    const float* bn2g = (const float*)d_in[22]; const float* bn2b = (const float*)d_in[23];
    const float* sw2 = (const float*)d_in[24];

    float* out = (float*)d_out;
    float* out_desc  = out;
    float* out_score = out + 64 * NN;

    k_qkv<<<89, 256>>>(desc1, desc2, qw, qb, kw, kb, vw, vb, mhw, mhb, cw1, cb1);
    k_AB<<<96, 256>>>(sw1, sb1, bn1g, bn1b);
    k_score<<<dim3(12, 12), 512>>>(sw2, shw, bn2g, bn2b, out_score);
    k_softmax<<<96, 256>>>(out_score);
    k_av<<<192, 256>>>(out_score);
    k_g1<<<48, 256>>>(cw1, desc1);
    k_final<<<24, 256>>>(cw2, cb2, cbg, cbb, desc1, out_desc);
}